// round 3
// baseline (speedup 1.0000x reference)
#include <cuda_runtime.h>
#include <cuda_bf16.h>

// ZBL basis: per-edge screened Coulomb repulsion with polynomial cutoff,
// scatter-summed into receiver nodes.
//
// Inputs (metadata order):
//   d_in[0]: x               float32 [E, 1]   (E = 3,200,000)
//   d_in[1]: node_attrs      float32 [N, 10]  (N = 100,000)
//   d_in[2]: edge_index      int32   [2, E]
//   d_in[3]: atomic_numbers  int32   [10]
//   d_in[4]: covalent_radii  float32 [119]
// Output: V_ZBL float32 [N]
//
// Only 10 distinct elements exist -> all Z-derived pair quantities are one of
// 100 values. Per-node we store the ELEMENT INDEX (u8); per-edge work is then
// 2x LDS.U8 + 1x LDS.128 into a 100-entry float4 pair LUT:
//   pair = (inv_rmax, invA, 0.5*14.3996*Zu*Zv, pad)

#define MAX_NODES 100352   // >= N, multiple of 4 for word copies
#define N_ELEMS   10

__device__ unsigned char g_e[MAX_NODES];   // per-node element index 0..9

__device__ __forceinline__ float ex2f(float a) {
    float r; asm("ex2.approx.f32 %0, %1;" : "=f"(r) : "f"(a)); return r;
}
__device__ __forceinline__ float frcpf(float a) {
    float r; asm("rcp.approx.f32 %0, %1;" : "=f"(r) : "f"(a)); return r;
}

// ---------------------------------------------------------------------------
// Node prep: argmax over 10 attrs -> element index (u8); zero the output.
// ---------------------------------------------------------------------------
__global__ void node_prep_kernel(const float* __restrict__ attrs,
                                 float* __restrict__ out,
                                 int n_nodes, int out_n) {
    __shared__ float s[256 * N_ELEMS];
    int base = blockIdx.x * 256;
    int nloc = n_nodes - base;
    if (nloc > 256) nloc = 256;
    if (nloc > 0) {
        int total = nloc * N_ELEMS;
        const float* src = attrs + (size_t)base * N_ELEMS;
        for (int k = threadIdx.x; k < total; k += 256) s[k] = src[k];
    }
    __syncthreads();

    int i = base + threadIdx.x;
    if ((int)threadIdx.x < nloc) {
        const float* a = s + threadIdx.x * N_ELEMS;
        int best = 0;
        float bv = a[0];
#pragma unroll
        for (int j = 1; j < N_ELEMS; j++) {
            float v = a[j];
            if (v > bv) { bv = v; best = j; }
        }
        g_e[i] = (unsigned char)best;
    }
    if (i < out_n) out[i] = 0.0f;
}

// ---------------------------------------------------------------------------
// Edge kernel
// ---------------------------------------------------------------------------
__device__ __forceinline__ void process_edge(
    int s, int r, float xi,
    const unsigned char* __restrict__ s_e,
    const float4* __restrict__ s_pair,
    float* __restrict__ out)
{
    int eu = s_e[s];
    int ev = s_e[r];
    float4 p = s_pair[eu * N_ELEMS + ev];   // (inv_rmax, invA, pref, -)
    float rr = xi * p.x;
    if (rr < 1.0f) {
        float t = xi * p.y;
        // exp(-c*t) as ex2((-c*log2e) * t); constants folded at compile time
        const float K0 = -3.2f    * 1.44269504f;
        const float K1 = -0.9423f * 1.44269504f;
        const float K2 = -0.4028f * 1.44269504f;
        const float K3 = -0.2016f * 1.44269504f;
        float phi = 0.1818f  * ex2f(K0 * t)
                  + 0.5099f  * ex2f(K1 * t)
                  + 0.2802f  * ex2f(K2 * t)
                  + 0.02817f * ex2f(K3 * t);
        float v = p.z * phi * frcpf(xi);

        // polynomial envelope, p=6: 1 - 28 r^6 + 48 r^7 - 21 r^8
        float r2 = rr * rr;
        float r3 = r2 * rr;
        float r6 = r3 * r3;
        float env = fmaf(-28.0f, r6, 1.0f);
        env = fmaf(48.0f, r6 * rr, env);
        env = fmaf(-21.0f, r6 * r2, env);

        atomicAdd(out + r, v * env);
    }
}

__global__ void edge_kernel(const float* __restrict__ x,
                            const int* __restrict__ ei,
                            const int* __restrict__ atomic_numbers,
                            const float* __restrict__ radii_g,
                            float* __restrict__ out,
                            int n_edges, int n_nodes) {
    extern __shared__ char smem[];
    float4* s_pair = (float4*)smem;                         // 100 entries
    unsigned char* s_e = (unsigned char*)(s_pair + N_ELEMS * N_ELEMS);

    int tid = threadIdx.x;
    int nt = blockDim.x;

    // Build pair LUT: (inv_rmax, invA, pref)
    if (tid < N_ELEMS * N_ELEMS) {
        int i = tid / N_ELEMS, j = tid % N_ELEMS;
        int Zi = atomic_numbers[i], Zj = atomic_numbers[j];
        float Zif = (float)Zi, Zjf = (float)Zj;
        float inv_rmax = 1.0f / (radii_g[Zi] + radii_g[Zj]);
        float invA = (powf(Zif, 0.3f) + powf(Zjf, 0.3f))
                     * (1.0f / (0.4543f * 0.529f));
        float pref = 0.5f * 14.3996f * Zif * Zjf;
        s_pair[tid] = make_float4(inv_rmax, invA, pref, 0.0f);
    }
    // Copy element-index table into smem (word-wide, coalesced, L2-resident)
    {
        const unsigned int* ge32 = (const unsigned int*)g_e;
        unsigned int* se32 = (unsigned int*)s_e;
        int nwords = (n_nodes + 3) >> 2;
        for (int w = tid; w < nwords; w += nt) se32[w] = ge32[w];
    }
    __syncthreads();

    const int4*   si = (const int4*)ei;
    const int4*   ri = (const int4*)(ei + n_edges);
    const float4* x4 = (const float4*)x;
    int n4 = n_edges >> 2;
    int gstride = gridDim.x * nt;

    for (int g = blockIdx.x * nt + tid; g < n4; g += gstride) {
        int4 ss = si[g];
        int4 rr = ri[g];
        float4 xx = x4[g];
        process_edge(ss.x, rr.x, xx.x, s_e, s_pair, out);
        process_edge(ss.y, rr.y, xx.y, s_e, s_pair, out);
        process_edge(ss.z, rr.z, xx.z, s_e, s_pair, out);
        process_edge(ss.w, rr.w, xx.w, s_e, s_pair, out);
    }
    // scalar tail
    for (int i = (n4 << 2) + blockIdx.x * nt + tid; i < n_edges; i += gstride) {
        process_edge(ei[i], ei[n_edges + i], x[i], s_e, s_pair, out);
    }
}

extern "C" void kernel_launch(void* const* d_in, const int* in_sizes, int n_in,
                              void* d_out, int out_size) {
    const float* x              = (const float*)d_in[0];
    const float* node_attrs     = (const float*)d_in[1];
    const int*   edge_index     = (const int*)  d_in[2];
    const int*   atomic_numbers = (const int*)  d_in[3];
    const float* covalent_radii = (const float*)d_in[4];
    float* out = (float*)d_out;

    int n_edges = in_sizes[0];            // E
    int n_nodes = in_sizes[1] / N_ELEMS;  // N

    {
        int cover = n_nodes > out_size ? n_nodes : out_size;
        int blocks = (cover + 255) / 256;
        node_prep_kernel<<<blocks, 256>>>(node_attrs, out, n_nodes, out_size);
    }

    int smem_bytes = N_ELEMS * N_ELEMS * (int)sizeof(float4) + MAX_NODES;
    cudaFuncSetAttribute(edge_kernel,
                         cudaFuncAttributeMaxDynamicSharedMemorySize,
                         smem_bytes);
    edge_kernel<<<304, 1024, smem_bytes>>>(x, edge_index, atomic_numbers,
                                           covalent_radii, out,
                                           n_edges, n_nodes);
}